// round 2
// baseline (speedup 1.0000x reference)
#include <cuda_runtime.h>
#include <cstdint>

// out[mu[k], e] += X1[m1[k], e] * X2[m2[k], e] * mult[k]
// M=9 channels, K~100 terms, ND = N*D = 1M elements, fp32.
//
// Single fused kernel:
//  - TMA (cp.async.bulk) stages 18 channel-tiles (X1,X2) into smem.
//  - While TMA is in flight, all threads redundantly rank-sort the K terms by
//    (mu,m1,m2) and build (mu,m1) cells so the inner loop is
//        out[mu] += X1[m1] * (sum_cell mult * X2[m2])
//    cutting X1 smem reads from K to #cells (~58 for K=100).
//  - mu-segments are contiguous -> scalar float4 accumulator, coalesced STG.

#define M_CH    9
#define TILE    1024                  // floats per channel per block
#define TILE_B  (TILE * 4)            // 4096 bytes
#define THREADS 256
#define MAXK    128

struct SmemLayout {
    float4 sx[2 * M_CH * (TILE / 4)];   // 73728 B : X1 tiles then X2 tiles
    int2   term[MAXK];                  // sorted {off2_bytes, mult_bits}
    int    celloff[MAXK];               // raw keys, then per-cell off1_bytes
    int    cnt[MAXK];                   // per-cell term count
    int    key[MAXK];                   // sorted keys
    int    cellseg[M_CH + 2];           // cell range per mu
    unsigned long long mbar;
};

__global__ void __launch_bounds__(THREADS, 3)
fused_kernel(const float* __restrict__ X1, const float* __restrict__ X2,
             const int* __restrict__ m1, const int* __restrict__ m2,
             const int* __restrict__ mu, const float* __restrict__ mult,
             float* __restrict__ out, int nd4, int K)
{
    extern __shared__ char smem_raw[];
    SmemLayout* s = (SmemLayout*)smem_raw;
    const int t = threadIdx.x;
    const int base4 = blockIdx.x * (TILE / 4);

    const uint32_t mbar_addr = (uint32_t)__cvta_generic_to_shared(&s->mbar);

    // ---- phase 0: raw keys + mbarrier init --------------------------------
    if (t < MAXK) s->cnt[t] = 0;
    if (t < K) {
        int key = (mu[t] << 8) | (m1[t] << 4) | m2[t];
        s->celloff[t] = key;                       // raw key scratch
    }
    if (t == 0) {
        asm volatile("mbarrier.init.shared.b64 [%0], %1;"
                     :: "r"(mbar_addr), "r"(1) : "memory");
        asm volatile("fence.proxy.async.shared::cta;" ::: "memory");
    }
    __syncthreads();

    // ---- phase 1: issue TMA stage (thread 0), everyone else sorts ---------
    if (t == 0) {
        const uint32_t bytes = 2 * M_CH * TILE_B;
        asm volatile("mbarrier.arrive.expect_tx.shared.b64 _, [%0], %1;"
                     :: "r"(mbar_addr), "r"(bytes) : "memory");
        uint32_t dst = (uint32_t)__cvta_generic_to_shared(&s->sx[0]);
        const char* src1 = (const char*)(X1 + (size_t)base4 * 4);
        const char* src2 = (const char*)(X2 + (size_t)base4 * 4);
        const size_t chanstride = (size_t)nd4 * 16;
        const uint32_t csz = TILE_B;
#pragma unroll
        for (int m = 0; m < M_CH; m++) {
            asm volatile(
                "cp.async.bulk.shared::cta.global.mbarrier::complete_tx::bytes "
                "[%0], [%1], %2, [%3];"
                :: "r"(dst + m * TILE_B), "l"(src1 + m * chanstride),
                   "r"(csz), "r"(mbar_addr) : "memory");
            asm volatile(
                "cp.async.bulk.shared::cta.global.mbarrier::complete_tx::bytes "
                "[%0], [%1], %2, [%3];"
                :: "r"(dst + (M_CH + m) * TILE_B), "l"(src2 + m * chanstride),
                   "r"(csz), "r"(mbar_addr) : "memory");
        }
    }

    // stable rank sort by key (O(K) per thread, K<=128)
    if (t < K) {
        const int mykey = s->celloff[t];
        int r = 0;
        for (int j = 0; j < K; j++) {
            int kj = s->celloff[j];
            r += (kj < mykey) | ((kj == mykey) & (j < t));
        }
        s->key[r] = mykey;
        int2 tv;
        tv.x = M_CH * TILE_B + (mykey & 15) * TILE_B;   // X2 smem byte offset
        tv.y = __float_as_int(mult[t]);
        s->term[r] = tv;
    }
    __syncthreads();

    // ---- phase 2: build (mu,m1) cells from sorted keys --------------------
    if (t < K) {
        const int ck = s->key[t] >> 4;                  // (mu,m1) cell key
        const int head = (t == 0) || ((s->key[t - 1] >> 4) != ck);
        int cid = 0;
        for (int j = 1; j <= t; j++)
            cid += ((s->key[j] >> 4) != (s->key[j - 1] >> 4));
        atomicAdd(&s->cnt[cid], 1);
        if (head) s->celloff[cid] = (ck & 15) * TILE_B; // X1 smem byte offset
    }
    if (t <= M_CH) {
        int c = 0;
        for (int j = 0; j < K; j++) {
            int head = (j == 0) || ((s->key[j] >> 4) != (s->key[j - 1] >> 4));
            c += head & (int)((s->key[j] >> 8) < t);
        }
        s->cellseg[t] = c;
    }
    __syncthreads();

    // ---- wait for TMA data ------------------------------------------------
    asm volatile(
        "{\n\t.reg .pred P;\n\t"
        "WAIT_%=:\n\t"
        "mbarrier.try_wait.parity.acquire.cta.shared::cta.b64 P, [%0], 0, 0x989680;\n\t"
        "@P bra.uni DONE_%=;\n\t"
        "bra.uni WAIT_%=;\n\t"
        "DONE_%=:\n\t}"
        :: "r"(mbar_addr) : "memory");

    // ---- main loop --------------------------------------------------------
    const char* sb = (const char*)(&s->sx[0]) + t * 16;   // this thread's column
    float4* __restrict__ out4 = (float4*)out;
    int kptr = 0;

#pragma unroll
    for (int m = 0; m < M_CH; m++) {
        float4 acc = make_float4(0.f, 0.f, 0.f, 0.f);
        const int c0 = s->cellseg[m];
        const int c1 = s->cellseg[m + 1];
        for (int c = c0; c < c1; c++) {
            const int off1 = s->celloff[c];
            const int cnum = s->cnt[c];
            float4 a = *(const float4*)(sb + off1);       // 1 LDS.128 per cell
            float4 tsum = make_float4(0.f, 0.f, 0.f, 0.f);
            for (int j = 0; j < cnum; j++) {
                int2 tm = s->term[kptr + j];              // broadcast LDS.64
                float4 b = *(const float4*)(sb + tm.x);   // 1 LDS.128 per term
                float mlt = __int_as_float(tm.y);
                tsum.x = fmaf(mlt, b.x, tsum.x);
                tsum.y = fmaf(mlt, b.y, tsum.y);
                tsum.z = fmaf(mlt, b.z, tsum.z);
                tsum.w = fmaf(mlt, b.w, tsum.w);
            }
            kptr += cnum;
            acc.x = fmaf(a.x, tsum.x, acc.x);
            acc.y = fmaf(a.y, tsum.y, acc.y);
            acc.z = fmaf(a.z, tsum.z, acc.z);
            acc.w = fmaf(a.w, tsum.w, acc.w);
        }
        out4[(size_t)m * nd4 + base4 + t] = acc;          // coalesced STG.128
    }
}

extern "C" void kernel_launch(void* const* d_in, const int* in_sizes, int n_in,
                              void* d_out, int out_size)
{
    const float* X1   = (const float*)d_in[0];
    const float* X2   = (const float*)d_in[1];
    const int*   m1   = (const int*)d_in[2];
    const int*   m2   = (const int*)d_in[3];
    const int*   mu   = (const int*)d_in[4];
    const float* mult = (const float*)d_in[5];
    float*       out  = (float*)d_out;

    const int K   = in_sizes[2];
    const int ND  = in_sizes[0] / M_CH;      // N*D
    const int nd4 = ND / 4;

    const int smem = (int)sizeof(SmemLayout);
    cudaFuncSetAttribute(fused_kernel,
                         cudaFuncAttributeMaxDynamicSharedMemorySize, smem);

    fused_kernel<<<ND / TILE, THREADS, smem>>>(X1, X2, m1, m2, mu, mult,
                                               out, nd4, K);
}

// round 3
// speedup vs baseline: 1.1756x; 1.1756x over previous
#include <cuda_runtime.h>
#include <cstdint>

// out[mu[k], e] += X1[m1[k], e] * X2[m2[k], e] * mult[k]
// M=9 channels, K~100 terms (runtime), ND = N*D = 2^20 elements, fp32.
//
// One fused kernel:
//   - TMA (cp.async.bulk) stages 18 channel tiles into smem.
//   - Hidden behind the TMA: all threads rank-sort the K terms by (mu,m1,m2)
//     and build a PADDED program: per-mu segments padded to a multiple of 4
//     with mult=0 dummies; term = {off1, off2, mult_bits, reload_flag}.
//   - Main loop: 9 segments, stride-4 unrolled flat term loop; X1 operand 'a'
//     is register-cached and reloaded only when (mu,m1) changes (predicated
//     LDS); math uses packed f32x2 FMA to halve fma-pipe issue.

#define M_CH    9
#define TILE    512                    // floats per channel per block
#define TILE_B  (TILE * 4)             // 2048 bytes
#define THREADS 128
#define MAXK    128
#define PROGMAX 160                    // K + 9*3 pads max, rounded up

struct Smem {
    float4 sx[2 * M_CH * (TILE / 4)];  // 36864 B: X1 tiles then X2 tiles
    int4   prog[PROGMAX];              // padded program
    int    rawkey[MAXK];
    int    skey[MAXK];
    int    smlt[MAXK];
    int    seg[M_CH + 1];
    int    pseg[M_CH + 1];
    unsigned long long mbar;
};

__global__ void __launch_bounds__(THREADS, 5)
fused_kernel(const float* __restrict__ X1, const float* __restrict__ X2,
             const int* __restrict__ m1, const int* __restrict__ m2,
             const int* __restrict__ mu, const float* __restrict__ mult,
             float* __restrict__ out, int nd4, int K)
{
    __shared__ Smem s;
    const int t = threadIdx.x;
    const int base4 = blockIdx.x * (TILE / 4);
    const uint32_t mbar_addr = (uint32_t)__cvta_generic_to_shared(&s.mbar);

    // ---- phase 0: raw keys, mbarrier init ---------------------------------
    if (t < K)
        s.rawkey[t] = (mu[t] << 8) | (m1[t] << 4) | m2[t];
    if (t == 0) {
        asm volatile("mbarrier.init.shared.b64 [%0], %1;"
                     :: "r"(mbar_addr), "r"(1) : "memory");
        asm volatile("fence.proxy.async.shared::cta;" ::: "memory");
    }
    __syncthreads();

    // ---- phase 1: TMA issue (t0) + rank sort + seg histogram --------------
    if (t == 0) {
        const uint32_t bytes = 2 * M_CH * TILE_B;
        asm volatile("mbarrier.arrive.expect_tx.shared.b64 _, [%0], %1;"
                     :: "r"(mbar_addr), "r"(bytes) : "memory");
        uint32_t dst = (uint32_t)__cvta_generic_to_shared(&s.sx[0]);
        const char* src1 = (const char*)(X1 + (size_t)base4 * 4);
        const char* src2 = (const char*)(X2 + (size_t)base4 * 4);
        const size_t chanstride = (size_t)nd4 * 16;
#pragma unroll
        for (int m = 0; m < M_CH; m++) {
            asm volatile(
                "cp.async.bulk.shared::cta.global.mbarrier::complete_tx::bytes "
                "[%0], [%1], %2, [%3];"
                :: "r"(dst + m * TILE_B), "l"(src1 + m * chanstride),
                   "r"((uint32_t)TILE_B), "r"(mbar_addr) : "memory");
            asm volatile(
                "cp.async.bulk.shared::cta.global.mbarrier::complete_tx::bytes "
                "[%0], [%1], %2, [%3];"
                :: "r"(dst + (M_CH + m) * TILE_B), "l"(src2 + m * chanstride),
                   "r"((uint32_t)TILE_B), "r"(mbar_addr) : "memory");
        }
    }
    if (t < K) {
        const int mykey = s.rawkey[t];
        int r = 0;
        for (int j = 0; j < K; j++) {
            int kj = s.rawkey[j];
            r += (kj < mykey) | ((kj == mykey) & (j < t));
        }
        s.skey[r] = mykey;
        s.smlt[r] = __float_as_int(mult[t]);
    }
    if (t <= M_CH) {           // seg[m] = #{k : mu_k < m}
        int c = 0;
        for (int j = 0; j < K; j++) c += ((s.rawkey[j] >> 8) < t);
        s.seg[t] = c;
    }
    __syncthreads();

    // ---- phase 2a: padded segment starts + dummy terms (t0, tiny serial) --
    if (t == 0) {
        int p = 0;
        for (int m = 0; m < M_CH; m++) {
            s.pseg[m] = p;
            int len  = s.seg[m + 1] - s.seg[m];
            int plen = (len + 3) & ~3;
            for (int d = len; d < plen; d++)       // inert pads: mult=0
                s.prog[p + d] = make_int4(0, 0, 0, 0);
            p += plen;
        }
        s.pseg[M_CH] = p;
    }
    __syncthreads();

    // ---- phase 2b: scatter real terms into padded program -----------------
    if (t < K) {
        const int key = s.skey[t];
        const int m   = key >> 8;
        const int pos = s.pseg[m] + (t - s.seg[m]);
        const int reload = (t == 0) || ((s.skey[t - 1] >> 4) != (key >> 4));
        int4 v;
        v.x = ((key >> 4) & 15) * TILE_B;                  // X1 smem offset
        v.y = M_CH * TILE_B + (key & 15) * TILE_B;         // X2 smem offset
        v.z = s.smlt[t];
        v.w = reload;
        s.prog[pos] = v;
    }
    __syncthreads();

    // ---- wait for TMA -----------------------------------------------------
    asm volatile(
        "{\n\t.reg .pred P;\n\t"
        "W_%=:\n\t"
        "mbarrier.try_wait.parity.acquire.cta.shared::cta.b64 P, [%0], 0, 0x989680;\n\t"
        "@P bra.uni D_%=;\n\t"
        "bra.uni W_%=;\n\t"
        "D_%=:\n\t}"
        :: "r"(mbar_addr) : "memory");

    // ---- main loop --------------------------------------------------------
    const char* sb = (const char*)(&s.sx[0]) + t * 16;
    const size_t gcol = (size_t)base4 + t;
    ulonglong2 a; a.x = 0ull; a.y = 0ull;
    int kptr = 0;

#pragma unroll
    for (int m = 0; m < M_CH; m++) {
        ulonglong2 acc; acc.x = 0ull; acc.y = 0ull;
        const int k1 = s.pseg[m + 1];
        for (int k = kptr; k < k1; k += 4) {
#pragma unroll
            for (int u = 0; u < 4; u++) {
                int4 tm = s.prog[k + u];                       // broadcast LDS.128
                if (tm.w) a = *(const ulonglong2*)(sb + tm.x); // predicated LDS.128
                ulonglong2 b = *(const ulonglong2*)(sb + tm.y);
                unsigned long long c2;
                asm("mov.b64 %0, {%1, %1};" : "=l"(c2) : "r"(tm.z));
                asm("mul.rn.f32x2 %0, %1, %2;"     : "=l"(b.x) : "l"(c2),  "l"(b.x));
                asm("mul.rn.f32x2 %0, %1, %2;"     : "=l"(b.y) : "l"(c2),  "l"(b.y));
                asm("fma.rn.f32x2 %0, %1, %2, %3;" : "=l"(acc.x) : "l"(b.x), "l"(a.x), "l"(acc.x));
                asm("fma.rn.f32x2 %0, %1, %2, %3;" : "=l"(acc.y) : "l"(b.y), "l"(a.y), "l"(acc.y));
            }
        }
        kptr = k1;
        *(ulonglong2*)((float4*)out + (size_t)m * nd4 + gcol) = acc;  // STG.128
    }
}

extern "C" void kernel_launch(void* const* d_in, const int* in_sizes, int n_in,
                              void* d_out, int out_size)
{
    const float* X1   = (const float*)d_in[0];
    const float* X2   = (const float*)d_in[1];
    const int*   m1   = (const int*)d_in[2];
    const int*   m2   = (const int*)d_in[3];
    const int*   mu   = (const int*)d_in[4];
    const float* mult = (const float*)d_in[5];
    float*       out  = (float*)d_out;

    const int K   = in_sizes[2];
    const int ND  = in_sizes[0] / M_CH;    // N*D
    const int nd4 = ND / 4;

    fused_kernel<<<ND / TILE, THREADS>>>(X1, X2, m1, m2, mu, mult, out, nd4, K);
}